// round 9
// baseline (speedup 1.0000x reference)
#include <cuda_runtime.h>
#include <cuda_bf16.h>
#include <stdint.h>

#define N_NODES 50000
#define N_EDGES 200000
#define HID 32
#define M_TILES 391          // ceil(50000/128)
#define NBKT 1563            // ceil(50000/32) buckets of 32 source nodes
#define BCAP 2048
#define OVF_BLOCKS 8

// ---------------- device scratch (static allocation only) ----------------
__device__ int            g_is64;
__device__ int            g_src[N_EDGES], g_dst[N_EDGES];
__device__ float          g_hA[N_NODES * HID];
__device__ float          g_hB[N_NODES * HID];
__device__ unsigned short g_w2tb[1056 * 32];           // bf16 [col][h]; col=o*32+k, 1024+o=bias
__device__ unsigned       g_Yt[(size_t)N_NODES * 512]; // bf16x2 packed [n][o][k/2]
__device__ float          g_Yb[N_NODES * HID];         // bias image row (fp32)
__device__ float          g_agg[N_NODES * HID];
__device__ float          g_cnt[N_NODES];
__device__ int            g_bkt[NBKT * BCAP];          // src-bucketed edge ids
__device__ int            g_bcnt[NBKT];
__device__ int            g_ovf[N_EDGES];
__device__ int            g_ocnt;

// ---------------- edge_index dtype detection ----------------
__global__ __launch_bounds__(256) void detect_kernel(const void* ei) {
    const unsigned* u = (const unsigned*)ei;
    __shared__ int any;
    if (threadIdx.x == 0) any = 0;
    __syncthreads();
    int local = 0;
    for (int i = threadIdx.x; i < 8192; i += blockDim.x)
        if (u[2 * i + 1] != 0u) local = 1;
    if (local) atomicOr(&any, 1);
    __syncthreads();
    if (threadIdx.x == 0) g_is64 = (any == 0) ? 1 : 0;
}

__global__ __launch_bounds__(256) void normalize_edges(const void* ei) {
    int e = blockIdx.x * blockDim.x + threadIdx.x;
    if (e >= N_EDGES) return;
    int s, d;
    if (g_is64) {
        const long long* p = (const long long*)ei;
        s = (int)p[e];
        d = (int)p[N_EDGES + e];
    } else {
        const int* p = (const int*)ei;
        s = p[e];
        d = p[N_EDGES + e];
    }
    s = min(max(s, 0), N_NODES - 1);
    d = min(max(d, 0), N_NODES - 1);
    g_src[e] = s;
    g_dst[e] = d;
}

__global__ __launch_bounds__(256) void count_dst_kernel() {
    int e = blockIdx.x * blockDim.x + threadIdx.x;
    if (e >= N_EDGES) return;
    atomicAdd(&g_cnt[g_dst[e]], 1.f);
}

// bucket edges by src/32 (scan-free counting buckets; overflow-safe)
__global__ __launch_bounds__(256) void bucket_build_kernel() {
    int e = blockIdx.x * blockDim.x + threadIdx.x;
    if (e >= N_EDGES) return;
    int b = g_src[e] >> 5;
    int p = atomicAdd(&g_bcnt[b], 1);
    if (p < BCAP) {
        g_bkt[b * BCAP + p] = e;
    } else {
        int q = atomicAdd(&g_ocnt, 1);
        g_ovf[q] = e;
    }
}

// ---------------- h0 = relu(x @ Win + b) ------------------------------------
__global__ __launch_bounds__(256) void inproj_kernel(
    const float* __restrict__ x, const float* __restrict__ W,
    const float* __restrict__ b, float* __restrict__ hout) {
    __shared__ float sW[64 * 32];
    __shared__ float sb[32];
    int tid = threadIdx.x;
    for (int i = tid; i < 64 * 32; i += 256) sW[i] = W[i];
    if (tid < 32) sb[tid] = b[tid];
    __syncthreads();
    int lane = tid & 31, wid = tid >> 5;
    int n = blockIdx.x * 8 + wid;
    if (n >= N_NODES) return;
    float xa = x[n * 64 + lane];
    float xb = x[n * 64 + 32 + lane];
    float r = sb[lane];
#pragma unroll
    for (int k = 0; k < 32; k++)
        r = fmaf(__shfl_sync(0xffffffffu, xa, k), sW[k * 32 + lane], r);
#pragma unroll
    for (int k = 0; k < 32; k++)
        r = fmaf(__shfl_sync(0xffffffffu, xb, k), sW[(k + 32) * 32 + lane], r);
    hout[n * 32 + lane] = fmaxf(r, 0.f);
}

// ---------------- w2 repack to bf16 B^T: g_w2tb[col][h] ---------------------
__global__ __launch_bounds__(256) void w2tb_kernel(
    const float* __restrict__ w2, const float* __restrict__ b2) {
    int idx = blockIdx.x * 256 + threadIdx.x;  // 33792 total
    int col = idx >> 5, hh = idx & 31;
    float v;
    if (col < 1024) {
        int o = col >> 5, k = col & 31;
        v = w2[k * 1024 + hh * 32 + o];
    } else {
        int o = col - 1024;
        v = b2[hh * 32 + o];
    }
    __nv_bfloat16 bv = __float2bfloat16(v);
    g_w2tb[col * 32 + hh] = *reinterpret_cast<unsigned short*>(&bv);
}

// ---------------- Y via mma.sync bf16 HMMA ----------------------------------
__device__ __forceinline__ void hmma16816(float* c, uint32_t a0, uint32_t a1,
                                          uint32_t a2, uint32_t a3,
                                          uint32_t b0, uint32_t b1) {
    asm volatile(
        "mma.sync.aligned.m16n8k16.row.col.f32.bf16.bf16.f32 "
        "{%0,%1,%2,%3}, {%4,%5,%6,%7}, {%8,%9}, {%0,%1,%2,%3};"
        : "+f"(c[0]), "+f"(c[1]), "+f"(c[2]), "+f"(c[3])
        : "r"(a0), "r"(a1), "r"(a2), "r"(a3), "r"(b0), "r"(b1));
}

#define ASTR 36
#define BSTR 36

__global__ __launch_bounds__(256) void y_hmma_kernel(const float* __restrict__ h) {
    __shared__ __nv_bfloat16 sA[128 * ASTR];
    __shared__ __nv_bfloat16 sB[264 * BSTR];
    int tid = threadIdx.x, lane = tid & 31, wid = tid >> 5;
    int m0 = blockIdx.x * 128;
    int nb0 = blockIdx.y * 264;

    for (int idx = tid; idx < 128 * 32; idx += 256) {
        int r = idx >> 5, k = idx & 31;
        int n = m0 + r;
        float v = (n < N_NODES) ? __ldg(h + (size_t)n * 32 + k) : 0.f;
        sA[r * ASTR + k] = __float2bfloat16(v);
    }
    for (int idx = tid; idx < 264 * 32; idx += 256) {
        int r = idx >> 5, k = idx & 31;
        unsigned short us = g_w2tb[(nb0 + r) * 32 + k];
        sB[r * BSTR + k] = *reinterpret_cast<__nv_bfloat16*>(&us);
    }
    __syncthreads();

    int r = wid * 16 + (lane >> 2);
    int kc = (lane & 3) * 2;
    uint32_t A0[2], A1[2], A2[2], A3[2];
#pragma unroll
    for (int ch = 0; ch < 2; ch++) {
        int kb = ch * 16 + kc;
        A0[ch] = *reinterpret_cast<const uint32_t*>(sA + r * ASTR + kb);
        A1[ch] = *reinterpret_cast<const uint32_t*>(sA + (r + 8) * ASTR + kb);
        A2[ch] = *reinterpret_cast<const uint32_t*>(sA + r * ASTR + kb + 8);
        A3[ch] = *reinterpret_cast<const uint32_t*>(sA + (r + 8) * ASTR + kb + 8);
    }

    int n_row0 = m0 + r;
    int n_row1 = n_row0 + 8;
    int nloc_base = lane >> 2;

    for (int t = 0; t < 33; t++) {
        int nloc = t * 8 + nloc_base;
        float c[4] = {0.f, 0.f, 0.f, 0.f};
#pragma unroll
        for (int ch = 0; ch < 2; ch++) {
            int kb = ch * 16 + kc;
            uint32_t b0 = *reinterpret_cast<const uint32_t*>(sB + nloc * BSTR + kb);
            uint32_t b1 = *reinterpret_cast<const uint32_t*>(sB + nloc * BSTR + kb + 8);
            hmma16816(c, A0[ch], A1[ch], A2[ch], A3[ch], b0, b1);
        }
        int col = nb0 + t * 8 + kc;
        if (col < 1024) {
            int o = col >> 5, kk = col & 31;
            __nv_bfloat162 p0 = __floats2bfloat162_rn(c[0], c[1]);
            __nv_bfloat162 p1 = __floats2bfloat162_rn(c[2], c[3]);
            if (n_row0 < N_NODES)
                g_Yt[(size_t)n_row0 * 512 + o * 16 + (kk >> 1)] =
                    *reinterpret_cast<unsigned*>(&p0);
            if (n_row1 < N_NODES)
                g_Yt[(size_t)n_row1 * 512 + o * 16 + (kk >> 1)] =
                    *reinterpret_cast<unsigned*>(&p1);
        } else {
            int o = col - 1024;
            if (n_row0 < N_NODES)
                *reinterpret_cast<float2*>(g_Yb + (size_t)n_row0 * 32 + o) =
                    make_float2(c[0], c[1]);
            if (n_row1 < N_NODES)
                *reinterpret_cast<float2*>(g_Yb + (size_t)n_row1 * 32 + o) =
                    make_float2(c[2], c[3]);
        }
    }
}

// ---------------- edge body (shared by bucket + overflow paths) -------------
__device__ __forceinline__ void edge_body(int e, int lane, const float* sw1,
                                          const float* sb1,
                                          const float* __restrict__ ea,
                                          float* __restrict__ agg) {
    int s = g_src[e];
    int d = g_dst[e];

    const float4* eap = reinterpret_cast<const float4*>(ea + (size_t)e * 16);
    float acc = sb1[lane];
#pragma unroll
    for (int j = 0; j < 4; j++) {
        float4 av = __ldg(eap + j);
        acc = fmaf(av.x, sw1[(4 * j + 0) * 32 + lane], acc);
        acc = fmaf(av.y, sw1[(4 * j + 1) * 32 + lane], acc);
        acc = fmaf(av.z, sw1[(4 * j + 2) * 32 + lane], acc);
        acc = fmaf(av.w, sw1[(4 * j + 3) * 32 + lane], acc);
    }
    float he = fmaxf(acc, 0.f);

    float m0 = __ldg(g_Yb + (size_t)s * 32 + lane);
    float m1 = 0.f;
    const uint4* yp = reinterpret_cast<const uint4*>(g_Yt) + (size_t)s * 128 + lane * 4;
#pragma unroll
    for (int i = 0; i < 4; i++) {
        uint4 q = __ldg(yp + i);
        unsigned uu[4] = {q.x, q.y, q.z, q.w};
#pragma unroll
        for (int c = 0; c < 4; c++) {
            int k = i * 8 + c * 2;
            float lo = __int_as_float(uu[c] << 16);
            float hi = __int_as_float(uu[c] & 0xffff0000u);
            m0 = fmaf(__shfl_sync(0xffffffffu, he, k), lo, m0);
            m1 = fmaf(__shfl_sync(0xffffffffu, he, k + 1), hi, m1);
        }
    }
    atomicAdd(&agg[(size_t)d * 32 + lane], m0 + m1);
}

// ---------------- edge kernel: bucket per block (src-local Y reuse) ---------
__global__ __launch_bounds__(256) void edge_kernel(
    const float* __restrict__ ea, const float* __restrict__ w1,
    const float* __restrict__ b1, float* __restrict__ agg) {
    __shared__ float sw1[16 * 32];
    __shared__ float sb1[32];
    int tid = threadIdx.x, lane = tid & 31, wid = tid >> 5;
    for (int i = tid; i < 512; i += 256) sw1[i] = w1[i];
    if (tid < 32) sb1[tid] = b1[tid];
    __syncthreads();

    int nb = blockIdx.x;
    if (nb < NBKT) {
        int cnt = min(g_bcnt[nb], BCAP);
        const int* list = g_bkt + nb * BCAP;
        for (int idx = wid; idx < cnt; idx += 8)
            edge_body(list[idx], lane, sw1, sb1, ea, agg);
    } else {
        int total = g_ocnt;  // normally 0
        if (total > N_EDGES) total = N_EDGES;
        int gw = (nb - NBKT) * 8 + wid;
        for (int idx = gw; idx < total; idx += OVF_BLOCKS * 8)
            edge_body(g_ovf[idx], lane, sw1, sb1, ea, agg);
    }
}

// ---------------- node update: h' = relu(agg/cnt + h@rootW + rootb) ---------
__global__ __launch_bounds__(256) void node_update_kernel(
    const float* __restrict__ hin, const float* __restrict__ agg,
    const float* __restrict__ cnt, const float* __restrict__ rW,
    const float* __restrict__ rb, float* __restrict__ hout) {
    __shared__ float sW[32 * 32];
    __shared__ float sb[32];
    int tid = threadIdx.x;
    for (int i = tid; i < 1024; i += 256) sW[i] = rW[i];
    if (tid < 32) sb[tid] = rb[tid];
    __syncthreads();
    int lane = tid & 31, wid = tid >> 5;
    int n = blockIdx.x * 8 + wid;
    if (n >= N_NODES) return;
    float a = agg[n * 32 + lane] / fmaxf(cnt[n], 1.f);
    float hv = hin[n * 32 + lane];
    float r = sb[lane] + a;
#pragma unroll
    for (int k = 0; k < 32; k++)
        r = fmaf(__shfl_sync(0xffffffffu, hv, k), sW[k * 32 + lane], r);
    hout[n * 32 + lane] = fmaxf(r, 0.f);
}

// ---------------- fused head: z=h@Wo+bo; d1=relu(z@W1+b1); out=d1@W2+b2 -----
__global__ __launch_bounds__(256) void decoder_kernel(
    const float* __restrict__ h, const float* __restrict__ Wo,
    const float* __restrict__ bo, const float* __restrict__ W1,
    const float* __restrict__ b1, const float* __restrict__ W2,
    const float* __restrict__ b2, float* __restrict__ out) {
    __shared__ float sWo[32 * 16], sW1[16 * 32], sW2[32 * 64];
    __shared__ float sbo[16], sb1[32], sb2[64];
    int tid = threadIdx.x;
    for (int i = tid; i < 512; i += 256) { sWo[i] = Wo[i]; sW1[i] = W1[i]; }
    for (int i = tid; i < 2048; i += 256) sW2[i] = W2[i];
    if (tid < 16) sbo[tid] = bo[tid];
    if (tid < 32) sb1[tid] = b1[tid];
    if (tid < 64) sb2[tid] = b2[tid];
    __syncthreads();
    int lane = tid & 31, wid = tid >> 5;
    int n = blockIdx.x * 8 + wid;
    if (n >= N_NODES) return;
    float hv = h[n * 32 + lane];
    int l16 = lane & 15;
    float z = sbo[l16];
#pragma unroll
    for (int k = 0; k < 32; k++)
        z = fmaf(__shfl_sync(0xffffffffu, hv, k), sWo[k * 16 + l16], z);
    float d1 = sb1[lane];
#pragma unroll
    for (int j = 0; j < 16; j++)
        d1 = fmaf(__shfl_sync(0xffffffffu, z, j), sW1[j * 32 + lane], d1);
    d1 = fmaxf(d1, 0.f);
    float o0 = sb2[lane], o1 = sb2[32 + lane];
#pragma unroll
    for (int j = 0; j < 32; j++) {
        float dj = __shfl_sync(0xffffffffu, d1, j);
        o0 = fmaf(dj, sW2[j * 64 + lane], o0);
        o1 = fmaf(dj, sW2[j * 64 + 32 + lane], o1);
    }
    out[n * 64 + lane] = o0;
    out[n * 64 + 32 + lane] = o1;
}

// ---------------- launch ----------------
extern "C" void kernel_launch(void* const* d_in, const int* in_sizes, int n_in,
                              void* d_out, int out_size) {
    const float* x        = (const float*)d_in[0];
    const void*  ei       = d_in[1];
    const float* ea       = (const float*)d_in[2];
    const float* lin_in_w = (const float*)d_in[3];
    const float* lin_in_b = (const float*)d_in[4];
    const float* edge_w1  = (const float*)d_in[5];
    const float* edge_b1  = (const float*)d_in[6];
    const float* edge_w2  = (const float*)d_in[7];
    const float* edge_b2  = (const float*)d_in[8];
    const float* root_w   = (const float*)d_in[9];
    const float* root_b   = (const float*)d_in[10];
    const float* lout_w   = (const float*)d_in[11];
    const float* lout_b   = (const float*)d_in[12];
    const float* dec_w1   = (const float*)d_in[13];
    const float* dec_b1   = (const float*)d_in[14];
    const float* dec_w2   = (const float*)d_in[15];
    const float* dec_b2   = (const float*)d_in[16];
    float* out = (float*)d_out;

    void *p_agg, *p_cnt, *p_hA, *p_hB, *p_bcnt, *p_ocnt;
    cudaGetSymbolAddress(&p_agg, g_agg);
    cudaGetSymbolAddress(&p_cnt, g_cnt);
    cudaGetSymbolAddress(&p_hA, g_hA);
    cudaGetSymbolAddress(&p_hB, g_hB);
    cudaGetSymbolAddress(&p_bcnt, g_bcnt);
    cudaGetSymbolAddress(&p_ocnt, g_ocnt);
    float* hbuf[4] = {(float*)p_hA, (float*)p_hB, (float*)p_hA, (float*)p_hB};

    const int EB = (N_EDGES + 255) / 256;
    detect_kernel<<<1, 256>>>(ei);
    normalize_edges<<<EB, 256>>>(ei);
    cudaMemsetAsync(p_cnt, 0, (size_t)N_NODES * sizeof(float), 0);
    cudaMemsetAsync(p_bcnt, 0, (size_t)NBKT * sizeof(int), 0);
    cudaMemsetAsync(p_ocnt, 0, sizeof(int), 0);
    count_dst_kernel<<<EB, 256>>>();
    bucket_build_kernel<<<EB, 256>>>();

    const int NB = (N_NODES + 7) / 8;
    inproj_kernel<<<NB, 256>>>(x, lin_in_w, lin_in_b, (float*)p_hA);

    dim3 ygrid(M_TILES, 4);
    for (int L = 0; L < 3; L++) {
        const float* w1 = edge_w1 + L * 16 * 32;
        const float* b1 = edge_b1 + L * 32;
        const float* w2 = edge_w2 + L * 32 * 1024;
        const float* b2 = edge_b2 + L * 1024;
        const float* rw = root_w + L * 32 * 32;
        const float* rb = root_b + L * 32;
        const float* hin = hbuf[L];
        float* hout = hbuf[L + 1];

        w2tb_kernel<<<132, 256>>>(w2, b2);
        y_hmma_kernel<<<ygrid, 256>>>(hin);
        cudaMemsetAsync(p_agg, 0, (size_t)N_NODES * HID * sizeof(float), 0);
        edge_kernel<<<NBKT + OVF_BLOCKS, 256>>>(ea, w1, b1, (float*)p_agg);
        node_update_kernel<<<NB, 256>>>(hin, (const float*)p_agg,
                                        (const float*)p_cnt, rw, rb, hout);
    }
    decoder_kernel<<<NB, 256>>>(hbuf[3], lout_w, lout_b, dec_w1, dec_b1,
                                dec_w2, dec_b2, out);
}

// round 10
// speedup vs baseline: 1.1012x; 1.1012x over previous
#include <cuda_runtime.h>
#include <cuda_bf16.h>
#include <stdint.h>

#define N_NODES 50000
#define N_EDGES 200000
#define HID 32
#define M_TILES 391          // ceil(50000/128)
#define EGB 6250             // edge kernel blocks (4 edges/warp)

// ---------------- device scratch (static allocation only) ----------------
__device__ int            g_src[N_EDGES], g_dst[N_EDGES];
__device__ float          g_hA[N_NODES * HID];
__device__ float          g_hB[N_NODES * HID];
__device__ unsigned short g_w2tb[3 * 1056 * 32];       // bf16 [L][col][h]
__device__ unsigned       g_Yt[(size_t)N_NODES * 512]; // bf16x2 packed [n][o][k/2]
__device__ float          g_Yb[N_NODES * HID];         // bias image row (fp32)
__device__ float          g_agg[N_NODES * HID];
__device__ float          g_cnt[N_NODES];

// ---------------- fused pre: detect dtype + normalize + dst counts ----------
__global__ __launch_bounds__(256) void pre_kernel(const void* ei,
                                                  float* __restrict__ cnt) {
    __shared__ int any;
    if (threadIdx.x == 0) any = 0;
    __syncthreads();
    const unsigned* u = (const unsigned*)ei;
    int local = 0;
    for (int i = threadIdx.x; i < 2048; i += 256)
        if (u[2 * i + 1] != 0u) local = 1;
    if (local) atomicOr(&any, 1);
    __syncthreads();
    int is64 = (any == 0);

    int e = blockIdx.x * 256 + threadIdx.x;
    if (e >= N_EDGES) return;
    int s, d;
    if (is64) {
        const long long* p = (const long long*)ei;
        s = (int)p[e];
        d = (int)p[N_EDGES + e];
    } else {
        const int* p = (const int*)ei;
        s = p[e];
        d = p[N_EDGES + e];
    }
    s = min(max(s, 0), N_NODES - 1);
    d = min(max(d, 0), N_NODES - 1);
    g_src[e] = s;
    g_dst[e] = d;
    atomicAdd(&cnt[d], 1.f);
}

// ---------------- h0 = relu(x @ Win + b) ------------------------------------
__global__ __launch_bounds__(256) void inproj_kernel(
    const float* __restrict__ x, const float* __restrict__ W,
    const float* __restrict__ b, float* __restrict__ hout) {
    __shared__ float sW[64 * 32];
    __shared__ float sb[32];
    int tid = threadIdx.x;
    for (int i = tid; i < 64 * 32; i += 256) sW[i] = W[i];
    if (tid < 32) sb[tid] = b[tid];
    __syncthreads();
    int lane = tid & 31, wid = tid >> 5;
    int n = blockIdx.x * 8 + wid;
    if (n >= N_NODES) return;
    float xa = x[n * 64 + lane];
    float xb = x[n * 64 + 32 + lane];
    float r = sb[lane];
#pragma unroll
    for (int k = 0; k < 32; k++)
        r = fmaf(__shfl_sync(0xffffffffu, xa, k), sW[k * 32 + lane], r);
#pragma unroll
    for (int k = 0; k < 32; k++)
        r = fmaf(__shfl_sync(0xffffffffu, xb, k), sW[(k + 32) * 32 + lane], r);
    hout[n * 32 + lane] = fmaxf(r, 0.f);
}

// ---------------- w2 repack (all 3 layers, one launch) ----------------------
// g_w2tb[L][col][h]: col = o*32+k (k<32) -> w2[L][k][h*32+o]; col=1024+o -> b2[L][h*32+o]
__global__ __launch_bounds__(256) void w2tb_all_kernel(
    const float* __restrict__ edge_w2, const float* __restrict__ edge_b2) {
    int idx = blockIdx.x * 256 + threadIdx.x;
    if (idx >= 3 * 33792) return;
    int L = idx / 33792;
    int rem = idx - L * 33792;
    int col = rem >> 5, hh = rem & 31;
    const float* w2 = edge_w2 + L * 32768;
    const float* b2 = edge_b2 + L * 1024;
    float v;
    if (col < 1024) {
        int o = col >> 5, k = col & 31;
        v = w2[k * 1024 + hh * 32 + o];
    } else {
        v = b2[hh * 32 + (col - 1024)];
    }
    __nv_bfloat16 bv = __float2bfloat16(v);
    g_w2tb[idx] = *reinterpret_cast<unsigned short*>(&bv);
}

// ---------------- Y via mma.sync bf16 HMMA ----------------------------------
__device__ __forceinline__ void hmma16816(float* c, uint32_t a0, uint32_t a1,
                                          uint32_t a2, uint32_t a3,
                                          uint32_t b0, uint32_t b1) {
    asm volatile(
        "mma.sync.aligned.m16n8k16.row.col.f32.bf16.bf16.f32 "
        "{%0,%1,%2,%3}, {%4,%5,%6,%7}, {%8,%9}, {%0,%1,%2,%3};"
        : "+f"(c[0]), "+f"(c[1]), "+f"(c[2]), "+f"(c[3])
        : "r"(a0), "r"(a1), "r"(a2), "r"(a3), "r"(b0), "r"(b1));
}

#define ASTR 36
#define BSTR 36

__global__ __launch_bounds__(256) void y_hmma_kernel(
    const float* __restrict__ h, const unsigned short* __restrict__ w2tb) {
    __shared__ __nv_bfloat16 sA[128 * ASTR];
    __shared__ __nv_bfloat16 sB[264 * BSTR];
    int tid = threadIdx.x, lane = tid & 31, wid = tid >> 5;
    int m0 = blockIdx.x * 128;
    int nb0 = blockIdx.y * 264;

    for (int idx = tid; idx < 128 * 32; idx += 256) {
        int r = idx >> 5, k = idx & 31;
        int n = m0 + r;
        float v = (n < N_NODES) ? __ldg(h + (size_t)n * 32 + k) : 0.f;
        sA[r * ASTR + k] = __float2bfloat16(v);
    }
    for (int idx = tid; idx < 264 * 32; idx += 256) {
        int r = idx >> 5, k = idx & 31;
        unsigned short us = w2tb[(nb0 + r) * 32 + k];
        sB[r * BSTR + k] = *reinterpret_cast<__nv_bfloat16*>(&us);
    }
    __syncthreads();

    int r = wid * 16 + (lane >> 2);
    int kc = (lane & 3) * 2;
    uint32_t A0[2], A1[2], A2[2], A3[2];
#pragma unroll
    for (int ch = 0; ch < 2; ch++) {
        int kb = ch * 16 + kc;
        A0[ch] = *reinterpret_cast<const uint32_t*>(sA + r * ASTR + kb);
        A1[ch] = *reinterpret_cast<const uint32_t*>(sA + (r + 8) * ASTR + kb);
        A2[ch] = *reinterpret_cast<const uint32_t*>(sA + r * ASTR + kb + 8);
        A3[ch] = *reinterpret_cast<const uint32_t*>(sA + (r + 8) * ASTR + kb + 8);
    }

    int n_row0 = m0 + r;
    int n_row1 = n_row0 + 8;
    int nloc_base = lane >> 2;

    for (int t = 0; t < 33; t++) {
        int nloc = t * 8 + nloc_base;
        float c[4] = {0.f, 0.f, 0.f, 0.f};
#pragma unroll
        for (int ch = 0; ch < 2; ch++) {
            int kb = ch * 16 + kc;
            uint32_t b0 = *reinterpret_cast<const uint32_t*>(sB + nloc * BSTR + kb);
            uint32_t b1 = *reinterpret_cast<const uint32_t*>(sB + nloc * BSTR + kb + 8);
            hmma16816(c, A0[ch], A1[ch], A2[ch], A3[ch], b0, b1);
        }
        int col = nb0 + t * 8 + kc;
        if (col < 1024) {
            int o = col >> 5, kk = col & 31;
            __nv_bfloat162 p0 = __floats2bfloat162_rn(c[0], c[1]);
            __nv_bfloat162 p1 = __floats2bfloat162_rn(c[2], c[3]);
            if (n_row0 < N_NODES)
                g_Yt[(size_t)n_row0 * 512 + o * 16 + (kk >> 1)] =
                    *reinterpret_cast<unsigned*>(&p0);
            if (n_row1 < N_NODES)
                g_Yt[(size_t)n_row1 * 512 + o * 16 + (kk >> 1)] =
                    *reinterpret_cast<unsigned*>(&p1);
        } else {
            int o = col - 1024;
            if (n_row0 < N_NODES)
                *reinterpret_cast<float2*>(g_Yb + (size_t)n_row0 * 32 + o) =
                    make_float2(c[0], c[1]);
            if (n_row1 < N_NODES)
                *reinterpret_cast<float2*>(g_Yb + (size_t)n_row1 * 32 + o) =
                    make_float2(c[2], c[3]);
        }
    }
}

// ---------------- edge kernel: warp per edge (grid-stride x4) ---------------
__global__ __launch_bounds__(256) void edge_kernel(
    const float* __restrict__ ea, const float* __restrict__ w1,
    const float* __restrict__ b1, float* __restrict__ agg) {
    __shared__ float sw1[16 * 32];
    __shared__ float sb1[32];
    int tid = threadIdx.x, lane = tid & 31, wid = tid >> 5;
    for (int i = tid; i < 512; i += 256) sw1[i] = w1[i];
    if (tid < 32) sb1[tid] = b1[tid];
    __syncthreads();

    for (int e = blockIdx.x * 8 + wid; e < N_EDGES; e += EGB * 8) {
        int s = g_src[e];
        int d = g_dst[e];

        const float4* eap = reinterpret_cast<const float4*>(ea + (size_t)e * 16);
        float acc = sb1[lane];
#pragma unroll
        for (int j = 0; j < 4; j++) {
            float4 av = __ldg(eap + j);
            acc = fmaf(av.x, sw1[(4 * j + 0) * 32 + lane], acc);
            acc = fmaf(av.y, sw1[(4 * j + 1) * 32 + lane], acc);
            acc = fmaf(av.z, sw1[(4 * j + 2) * 32 + lane], acc);
            acc = fmaf(av.w, sw1[(4 * j + 3) * 32 + lane], acc);
        }
        float he = fmaxf(acc, 0.f);

        float m0 = __ldg(g_Yb + (size_t)s * 32 + lane);
        float m1 = 0.f;
        const uint4* yp =
            reinterpret_cast<const uint4*>(g_Yt) + (size_t)s * 128 + lane * 4;
#pragma unroll
        for (int i = 0; i < 4; i++) {
            uint4 q = __ldg(yp + i);
            unsigned uu[4] = {q.x, q.y, q.z, q.w};
#pragma unroll
            for (int c = 0; c < 4; c++) {
                int k = i * 8 + c * 2;
                float lo = __int_as_float(uu[c] << 16);
                float hi = __int_as_float(uu[c] & 0xffff0000u);
                m0 = fmaf(__shfl_sync(0xffffffffu, he, k), lo, m0);
                m1 = fmaf(__shfl_sync(0xffffffffu, he, k + 1), hi, m1);
            }
        }
        atomicAdd(&agg[(size_t)d * 32 + lane], m0 + m1);
    }
}

// ---------------- node update (+ agg reset; + fused decoder on last) --------
__global__ __launch_bounds__(256) void node_update_kernel(
    const float* __restrict__ hin, float* __restrict__ agg,
    const float* __restrict__ cnt, const float* __restrict__ rW,
    const float* __restrict__ rb, float* __restrict__ hout, int last,
    const float* __restrict__ Wo, const float* __restrict__ bo,
    const float* __restrict__ W1, const float* __restrict__ b1d,
    const float* __restrict__ W2, const float* __restrict__ b2d,
    float* __restrict__ out) {
    __shared__ float sW[32 * 32];
    __shared__ float sb[32];
    __shared__ float sWo[32 * 16], sW1[16 * 32], sW2[32 * 64];
    __shared__ float sbo[16], sb1[32], sb2[64];
    int tid = threadIdx.x;
    for (int i = tid; i < 1024; i += 256) sW[i] = rW[i];
    if (tid < 32) sb[tid] = rb[tid];
    if (last) {
        for (int i = tid; i < 512; i += 256) { sWo[i] = Wo[i]; sW1[i] = W1[i]; }
        for (int i = tid; i < 2048; i += 256) sW2[i] = W2[i];
        if (tid < 16) sbo[tid] = bo[tid];
        if (tid < 32) sb1[tid] = b1d[tid];
        if (tid < 64) sb2[tid] = b2d[tid];
    }
    __syncthreads();
    int lane = tid & 31, wid = tid >> 5;
    int n = blockIdx.x * 8 + wid;
    if (n >= N_NODES) return;

    float a = agg[n * 32 + lane] / fmaxf(cnt[n], 1.f);
    float hv = hin[n * 32 + lane];
    float r = sb[lane] + a;
#pragma unroll
    for (int k = 0; k < 32; k++)
        r = fmaf(__shfl_sync(0xffffffffu, hv, k), sW[k * 32 + lane], r);
    float hnew = fmaxf(r, 0.f);

    if (!last) {
        agg[n * 32 + lane] = 0.f;   // reset for next layer's atomics
        hout[n * 32 + lane] = hnew;
        return;
    }

    // fused decoder: z = h'@Wo+bo; d1 = relu(z@W1+b1); out = d1@W2+b2
    int l16 = lane & 15;
    float z = sbo[l16];
#pragma unroll
    for (int k = 0; k < 32; k++)
        z = fmaf(__shfl_sync(0xffffffffu, hnew, k), sWo[k * 16 + l16], z);
    float d1 = sb1[lane];
#pragma unroll
    for (int j = 0; j < 16; j++)
        d1 = fmaf(__shfl_sync(0xffffffffu, z, j), sW1[j * 32 + lane], d1);
    d1 = fmaxf(d1, 0.f);
    float o0 = sb2[lane], o1 = sb2[32 + lane];
#pragma unroll
    for (int j = 0; j < 32; j++) {
        float dj = __shfl_sync(0xffffffffu, d1, j);
        o0 = fmaf(dj, sW2[j * 64 + lane], o0);
        o1 = fmaf(dj, sW2[j * 64 + 32 + lane], o1);
    }
    out[n * 64 + lane] = o0;
    out[n * 64 + 32 + lane] = o1;
}

// ---------------- launch ----------------
extern "C" void kernel_launch(void* const* d_in, const int* in_sizes, int n_in,
                              void* d_out, int out_size) {
    const float* x        = (const float*)d_in[0];
    const void*  ei       = d_in[1];
    const float* ea       = (const float*)d_in[2];
    const float* lin_in_w = (const float*)d_in[3];
    const float* lin_in_b = (const float*)d_in[4];
    const float* edge_w1  = (const float*)d_in[5];
    const float* edge_b1  = (const float*)d_in[6];
    const float* edge_w2  = (const float*)d_in[7];
    const float* edge_b2  = (const float*)d_in[8];
    const float* root_w   = (const float*)d_in[9];
    const float* root_b   = (const float*)d_in[10];
    const float* lout_w   = (const float*)d_in[11];
    const float* lout_b   = (const float*)d_in[12];
    const float* dec_w1   = (const float*)d_in[13];
    const float* dec_b1   = (const float*)d_in[14];
    const float* dec_w2   = (const float*)d_in[15];
    const float* dec_b2   = (const float*)d_in[16];
    float* out = (float*)d_out;

    void *p_agg, *p_cnt, *p_hA, *p_hB, *p_w2tb;
    cudaGetSymbolAddress(&p_agg, g_agg);
    cudaGetSymbolAddress(&p_cnt, g_cnt);
    cudaGetSymbolAddress(&p_hA, g_hA);
    cudaGetSymbolAddress(&p_hB, g_hB);
    cudaGetSymbolAddress(&p_w2tb, g_w2tb);
    float* hbuf[4] = {(float*)p_hA, (float*)p_hB, (float*)p_hA, (float*)p_hB};

    cudaMemsetAsync(p_cnt, 0, (size_t)N_NODES * sizeof(float), 0);
    cudaMemsetAsync(p_agg, 0, (size_t)N_NODES * HID * sizeof(float), 0);

    const int EB = (N_EDGES + 255) / 256;
    pre_kernel<<<EB, 256>>>(ei, (float*)p_cnt);
    w2tb_all_kernel<<<(3 * 33792 + 255) / 256, 256>>>(edge_w2, edge_b2);

    const int NB = (N_NODES + 7) / 8;
    inproj_kernel<<<NB, 256>>>(x, lin_in_w, lin_in_b, (float*)p_hA);

    dim3 ygrid(M_TILES, 4);
    for (int L = 0; L < 3; L++) {
        const float* w1 = edge_w1 + L * 16 * 32;
        const float* b1 = edge_b1 + L * 32;
        const float* rw = root_w + L * 32 * 32;
        const float* rb = root_b + L * 32;
        const float* hin = hbuf[L];
        float* hout = hbuf[L + 1];
        const unsigned short* w2tbL =
            (const unsigned short*)p_w2tb + (size_t)L * 33792;

        y_hmma_kernel<<<ygrid, 256>>>(hin, w2tbL);
        edge_kernel<<<EGB, 256>>>(ea, w1, b1, (float*)p_agg);
        node_update_kernel<<<NB, 256>>>(hin, (float*)p_agg, (const float*)p_cnt,
                                        rw, rb, hout, (L == 2) ? 1 : 0,
                                        lout_w, lout_b, dec_w1, dec_b1,
                                        dec_w2, dec_b2, out);
    }
}